// round 17
// baseline (speedup 1.0000x reference)
#include <cuda_runtime.h>
#include <cuda_bf16.h>
#include <cstdint>

#define NUM_SKILLS 300
#define EMB 256
#define CD 64
#define D3 21          // skill / attempt encoder width
#define DM 22          // mastery encoder width
#define BATCH 512
#define SEQ 200
#define ROWS (BATCH * SEQ)
#define E4 (EMB / 4)              // 64 float4 lanes per position
#define TILE_S 20                 // positions per block; 10 tiles per row, no straddle
#define TILES_PER_ROW (SEQ / TILE_S)              // 10
#define TILE_BYTES (TILE_S * EMB * 4)             // 20480
#define SPT 5                     // positions per thread-group member (20 / 4 groups)

// Collapsed projection coefficients (device globals — no allocs allowed)
__device__ __align__(16) float4 g_cA4[E4];
__device__ __align__(16) float4 g_cB4[E4];
__device__ __align__(16) float4 g_cC4[E4];
__device__ __align__(16) float4 g_cD4[E4];

__device__ __forceinline__ uint32_t smem_u32(const void* p) {
    uint32_t a;
    asm("{ .reg .u64 tmp; cvta.to.shared.u64 tmp, %1; cvt.u32.u64 %0, tmp; }"
        : "=r"(a) : "l"(p));
    return a;
}

// ---------------------------------------------------------------------------
// Kernel 1 (1 block): collapse projection -> traj[e] = qf*A + att*B + mast*C + D
// ---------------------------------------------------------------------------
__global__ __launch_bounds__(256)
void coef_kernel(const float* __restrict__ skill_w, const float* __restrict__ skill_b,
                 const float* __restrict__ att_w,   const float* __restrict__ att_b,
                 const float* __restrict__ mast_w,  const float* __restrict__ mast_b,
                 const float* __restrict__ proj_w,  const float* __restrict__ proj_b) {
    const int t = threadIdx.x;
    const float4* P4 = reinterpret_cast<const float4*>(proj_w + t * CD); // [EMB,64] row-major
    float A = 0.f, Bv = 0.f, Cv = 0.f, D = __ldg(proj_b + t);
    #pragma unroll
    for (int i = 0; i < CD / 4; ++i) {
        const float4 v4 = __ldg(P4 + i);
        const float pe[4] = {v4.x, v4.y, v4.z, v4.w};
        #pragma unroll
        for (int j = 0; j < 4; ++j) {
            const int c = 4 * i + j;                // compile-time constant
            if (c < D3) {
                A = fmaf(__ldg(skill_w + c),          pe[j], A);
                D = fmaf(__ldg(skill_b + c),          pe[j], D);
            } else if (c < 2 * D3) {
                Bv = fmaf(__ldg(att_w + (c - D3)),    pe[j], Bv);
                D  = fmaf(__ldg(att_b + (c - D3)),    pe[j], D);
            } else {
                Cv = fmaf(__ldg(mast_w + (c - 2*D3)), pe[j], Cv);
                D  = fmaf(__ldg(mast_b + (c - 2*D3)), pe[j], D);
            }
        }
    }
    reinterpret_cast<float*>(g_cA4)[t] = A;
    reinterpret_cast<float*>(g_cB4)[t] = Bv;
    reinterpret_cast<float*>(g_cC4)[t] = Cv;
    reinterpret_cast<float*>(g_cD4)[t] = D;
}

// ---------------------------------------------------------------------------
// Kernel 2 (5120 blocks): counts + affine + smem tile + one 20KB bulk store.
// Block = (row b, tile j): positions [20j, 20j+20) of row b.
//   Phase 0: load row b's packed (q<<1)|r (or -2) into smem  [200 ints]
//   Phase 1: 20 threads scan their prefix -> att/mast/qf/vf  [<=200 LDS iters]
//   Phase 2: 256 threads: res = vf*(qf*A + att*B + mast*C + D) -> STS.128
//   Phase 3: thread 0: cp.async.bulk 20KB smem -> gmem (contiguous)
// ---------------------------------------------------------------------------
__global__ __launch_bounds__(256, 6)
void fused_kernel(const int* __restrict__ q, const int* __restrict__ r,
                  float* __restrict__ out) {
    __shared__ int   pk[SEQ];
    __shared__ float att_s[TILE_S], mast_s[TILE_S], qf_s[TILE_S], vf_s[TILE_S];
    __shared__ __align__(128) float4 tile[TILE_S * E4];   // 20 KB

    const int t   = threadIdx.x;
    const int row = blockIdx.x / TILES_PER_ROW;
    const int s0  = (blockIdx.x % TILES_PER_ROW) * TILE_S;

    // Coefs first: independent LDGs overlap with the row load + scan below.
    const int e4 = t & (E4 - 1);
    const float4 cA = g_cA4[e4];
    const float4 cB = g_cB4[e4];
    const float4 cC = g_cC4[e4];
    const float4 cD = g_cD4[e4];

    // ---- Phase 0: load row, pack key ----
    if (t < SEQ) {
        int qv = __ldg(q + row * SEQ + t);
        int rv = __ldg(r + row * SEQ + t);
        bool v = (qv >= 0) && (qv < NUM_SKILLS);
        pk[t] = v ? ((qv << 1) | (rv & 1)) : -2;
    }
    __syncthreads();

    // ---- Phase 1: prefix scan for this tile's 20 positions ----
    if (t < TILE_S) {
        const int pos = s0 + t;
        const int p0  = pk[pos];
        const int my  = p0 & ~1;
        int a = 0, c = 0;
        for (int tp = 0; tp <= pos; ++tp) {
            int p = pk[tp];
            bool hit = ((p & ~1) == my);
            a += hit;
            c += hit ? (p & 1) : 0;
        }
        const float af = (float)a;
        att_s[t]  = af;
        mast_s[t] = (float)c / fmaxf(af, 1.0f);
        qf_s[t]   = (float)(p0 >> 1);     // exact q for valid; irrelevant (x0) for invalid
        vf_s[t]   = (my >= 0) ? 1.0f : 0.0f;
    }
    __syncthreads();

    // ---- Phase 2: affine -> smem tile (STS.128, conflict-free) ----
    const int tg = t >> 6;                 // 0..3; positions tg, tg+4, ..., tg+16
    #pragma unroll
    for (int k = 0; k < SPT; ++k) {
        const int p = tg + 4 * k;          // warp-uniform
        const float a  = att_s[p];
        const float m  = mast_s[p];
        const float qf = qf_s[p];
        const float v  = vf_s[p];
        float4 res;
        res.x = v * fmaf(qf, cA.x, fmaf(a, cB.x, fmaf(m, cC.x, cD.x)));
        res.y = v * fmaf(qf, cA.y, fmaf(a, cB.y, fmaf(m, cC.y, cD.y)));
        res.z = v * fmaf(qf, cA.z, fmaf(a, cB.z, fmaf(m, cC.z, cD.z)));
        res.w = v * fmaf(qf, cA.w, fmaf(a, cB.w, fmaf(m, cC.w, cD.w)));
        tile[p * E4 + e4] = res;
    }
    __syncthreads();

    // ---- Phase 3: one bulk store of the whole tile ----
    if (t == 0) {
        asm volatile("fence.proxy.async.shared::cta;" ::: "memory");
        const uint32_t saddr = smem_u32(tile);
        float* gdst = out + ((size_t)row * SEQ + s0) * EMB;
        asm volatile(
            "cp.async.bulk.global.shared::cta.bulk_group [%0], [%1], %2;"
            :: "l"(gdst), "r"(saddr), "r"((uint32_t)TILE_BYTES) : "memory");
        asm volatile("cp.async.bulk.commit_group;" ::: "memory");
        asm volatile("cp.async.bulk.wait_group 0;" ::: "memory");
    }
}

extern "C" void kernel_launch(void* const* d_in, const int* in_sizes, int n_in,
                              void* d_out, int out_size) {
    const int*   q       = (const int*)d_in[0];
    const int*   r       = (const int*)d_in[1];
    /* d_in[2] = qry — unused by the reference computation */
    const float* skill_w = (const float*)d_in[3];
    const float* skill_b = (const float*)d_in[4];
    const float* att_w   = (const float*)d_in[5];
    const float* att_b   = (const float*)d_in[6];
    const float* mast_w  = (const float*)d_in[7];
    const float* mast_b  = (const float*)d_in[8];
    const float* proj_w  = (const float*)d_in[9];
    const float* proj_b  = (const float*)d_in[10];

    coef_kernel<<<1, 256>>>(skill_w, skill_b, att_w, att_b,
                            mast_w, mast_b, proj_w, proj_b);

    fused_kernel<<<BATCH * TILES_PER_ROW, 256>>>(q, r, (float*)d_out);  // 5120 blocks
}